// round 12
// baseline (speedup 1.0000x reference)
#include <cuda_runtime.h>
#include <cstdint>

// ---------------------------------------------------------------------------
// TractBundle: out = concat( x_a @ (Wa*Ma)^T, x_b @ (Wb*Mb)^T, x_c @ (Wc*Mc)^T )
// Masks: 64/64/32-sparse per row -> compressed sparse-gather.
// R9: R8 grouped-contiguous tables + (a) L1 prefetch of next pass's table
// stream, (b) boundary loads one pass ahead, (c) even-padded segments so the
// gather loop is a pure int4 stream.
// ---------------------------------------------------------------------------

#define CHUNK 256                   // src elements staged per pass
#define S     66                    // smem row stride (EVEN: float2 alignment)
#define TOKS  64                    // tokens per block (2 per lane, float2)
#define NDST  512                   // dst columns per block
#define DPW   16                    // dsts per warp (= group size)
#define BUFW  (CHUNK * S)           // 16896 floats per buffer
#define SMEM_BYTES (2 * BUFW * 4)   // 135168
#define SPLS  280                   // gspl stride per group (>= 16*16+17)
#define CAPAB 1280                  // entries per group, A/B (16*(64+16) padded)
#define CAPC  640                   // entries per group, C   (16*(32+8)  padded)

// Grouped tables: group g (16 dsts) owns a contiguous stream ordered
// (pass, dst)-major; every (dst,pass) segment is padded to EVEN length with
// (0, 0.0f) entries. Entry = ( (src%CHUNK)*S , bits(w*m) ).
// gspl[g*SPLS + p*16 + d] = group-relative segment start; positions
// [passes*16 .. passes*16+16] all hold the padded total (sentinel region).
__device__ __align__(16) int2 g_tabA[64 * CAPAB];
__device__ __align__(16) int2 g_tabB[32 * CAPAB];
__device__ __align__(16) int2 g_tabC[32 * CAPC];
__device__ int g_splA[64 * SPLS];
__device__ int g_splB[32 * SPLS];
__device__ int g_splC[32 * SPLS];

// ---------------------------------------------------------------------------
// Prep: one block per group of 16 dst rows (128 groups), 512 threads.
// count (padded even) -> serial (pass,dst)-major scan -> scatter + zero-pad.
// ---------------------------------------------------------------------------
__global__ __launch_bounds__(512)
void prep_grouped(const float* __restrict__ wa, const float* __restrict__ ma,
                  const float* __restrict__ wb, const float* __restrict__ mb,
                  const float* __restrict__ wc, const float* __restrict__ mc)
{
    __shared__ int soff[16][16];    // [dst][pass] group-relative offsets
    __shared__ int scnt[16][16];    // [dst][pass] padded counts
    __shared__ int s_run;

    const int tid  = threadIdx.x;
    const int lane = tid & 31;
    const int r    = tid >> 5;      // warp = row within group

    const float *W, *M; int2* tab; int* gspl;
    int src, group, cap;
    int gb = blockIdx.x;
    if (gb < 64)      { W = wa; M = ma; tab = g_tabA; gspl = g_splA;
                        src = 4096; group = gb;      cap = CAPAB; }
    else if (gb < 96) { W = wb; M = mb; tab = g_tabB; gspl = g_splB;
                        src = 4096; group = gb - 64; cap = CAPAB; }
    else              { W = wc; M = mc; tab = g_tabC; gspl = g_splC;
                        src = 2048; group = gb - 96; cap = CAPC; }

    const int passes = src / CHUNK;
    const int row = group * 16 + r;
    const float* wr = W + (size_t)row * src;
    const float* mr = M + (size_t)row * src;

    // ---- sweep 1: padded (even) nnz count per chunk ----
    for (int c = 0; c < passes; c++) {
        int cnt = 0;
#pragma unroll
        for (int i = 0; i < CHUNK / 32; i++)
            cnt += (mr[c * CHUNK + i * 32 + lane] != 0.0f);
#pragma unroll
        for (int o = 16; o; o >>= 1) cnt += __shfl_xor_sync(0xffffffffu, cnt, o);
        if (lane == 0) scnt[r][c] = (cnt + 1) & ~1;
    }
    __syncthreads();

    // ---- scan in (pass, dst)-major order ----
    if (tid == 0) {
        int run = 0;
        for (int p = 0; p < passes; p++)
            for (int d = 0; d < 16; d++) { soff[d][p] = run; run += scnt[d][p]; }
        s_run = run;
    }
    __syncthreads();

    // ---- write gspl (+ sentinel region) ----
    if (tid < passes * 16) {
        int p = tid >> 4, d = tid & 15;
        gspl[group * SPLS + p * 16 + d] = soff[d][p];
    }
    if (tid < 17) gspl[group * SPLS + passes * 16 + tid] = s_run;

    // ---- sweep 2: scatter entries + zero-pad odd segments ----
    int2* tg = tab + (size_t)group * cap;
    for (int c = 0; c < passes; c++) {
        int start = soff[r][c];
        int base = start;
        for (int i = 0; i < CHUNK / 32; i++) {
            int s = c * CHUNK + i * 32 + lane;
            float mv = mr[s];
            unsigned bits = __ballot_sync(0xffffffffu, mv != 0.0f);
            if (mv != 0.0f) {
                int pos = base + __popc(bits & ((1u << lane) - 1u));
                tg[pos] = make_int2((s & (CHUNK - 1)) * S, __float_as_int(wr[s] * mv));
            }
            base += __popc(bits);
        }
        if (lane == 0 && ((base - start) & 1))
            tg[base] = make_int2(0, 0);     // zero-weight pad -> even length
    }
}

// ---------------------------------------------------------------------------
// Fused gather kernel, 512 blocks x 1024 threads (32 warps).
//   [0,256)   tract A: tile = b>>1 (64-token tiles), dstblk = b&1
//   [256,384) tract B;  [384,512) tract C
// Warp w owns a 16-dst group; its per-pass table entries are one contiguous
// even-length int4 stream. Next pass's stream is L1-prefetched mid-pass, and
// its boundaries are loaded one pass ahead. Register-quarter x staging.
// ---------------------------------------------------------------------------
__global__ __launch_bounds__(1024, 1)
void tract_fused(const float* __restrict__ xa,
                 const float* __restrict__ xb,
                 const float* __restrict__ xc,
                 float* __restrict__ out)
{
    extern __shared__ float xs[];
    const int tid  = threadIdx.x;
    const int lane = tid & 31;
    const int wid  = tid >> 5;
    const int l17  = (lane < 17) ? lane : 16;

    // ---- block -> (tract, tile, dst block) dispatch ----
    const float* x; const int2* tab; const int* gspl;
    int src, passes, col_off, token0, dst_base, group, cap;
    int b = blockIdx.x;
    if (b < 256) {
        x = xa; tab = g_tabA; gspl = g_splA;
        src = 4096; passes = 16; cap = CAPAB;
        col_off = 0; token0 = (b >> 1) * TOKS; dst_base = (b & 1) * NDST;
        group = (b & 1) * 32 + wid;
    } else if (b < 384) {
        x = xb; tab = g_tabB; gspl = g_splB;
        src = 4096; passes = 16; cap = CAPAB;
        col_off = 1024; token0 = (b - 256) * TOKS; dst_base = 0;
        group = wid;
    } else {
        x = xc; tab = g_tabC; gspl = g_splC;
        src = 2048; passes = 8; cap = CAPC;
        col_off = 1536; token0 = (b - 384) * TOKS; dst_base = 0;
        group = wid;
    }

    const int2* tg    = tab + (size_t)group * cap;   // warp's stream
    const int* gspl_g = gspl + group * SPLS;
    const float* xr0 = x + (size_t)(token0 + 2 * wid) * src;
    const float* xr1 = xr0 + src;

    float2 st[2];                           // staged quarter (4 regs)

    // LDG quarter q (0..3) of chunk p
#define LDG_Q(p, q) do {                                                     \
        int _b = (p) * CHUNK + (q) * 64 + lane;                              \
        st[0] = make_float2(xr0[_b],      xr1[_b]);                          \
        st[1] = make_float2(xr0[_b + 32], xr1[_b + 32]);                     \
    } while (0)

    // STS quarter q into buffer bb (STS.64)
#define STS_Q(bb, q) do {                                                    \
        float* _d = xs + (bb) * BUFW + 2 * wid;                              \
        *(float2*)&_d[((q) * 64 + lane) * S]      = st[0];                   \
        *(float2*)&_d[((q) * 64 + lane + 32) * S] = st[1];                   \
    } while (0)

    // gather dsts [d0,d1): pure int4 stream (all segments even-length)
#define GATHER(d0, d1) do {                                                  \
        _Pragma("unroll")                                                    \
        for (int d = (d0); d < (d1); d++) {                                  \
            int e  = __shfl_sync(0xffffffffu, ev, d);                        \
            int e1 = __shfl_sync(0xffffffffu, ev, d + 1);                    \
            float a0x = 0.f, a0y = 0.f, a1x = 0.f, a1y = 0.f;                \
            for (; e < e1; e += 2) {                                         \
                int4 q = *(const int4*)&tg[e];                               \
                float2 xv0 = *(const float2*)(buf + q.x);                    \
                float2 xv1 = *(const float2*)(buf + q.z);                    \
                float w0 = __int_as_float(q.y);                              \
                float w1 = __int_as_float(q.w);                              \
                a0x = fmaf(w0, xv0.x, a0x);                                  \
                a0y = fmaf(w0, xv0.y, a0y);                                  \
                a1x = fmaf(w1, xv1.x, a1x);                                  \
                a1y = fmaf(w1, xv1.y, a1y);                                  \
            }                                                                \
            acc[d].x += a0x + a1x;                                           \
            acc[d].y += a0y + a1y;                                           \
        }                                                                    \
    } while (0)

    float2 acc[DPW];
#pragma unroll
    for (int d = 0; d < DPW; d++) acc[d] = make_float2(0.0f, 0.0f);

    // ---- prologue: stage chunk 0; load pass-0 boundaries ----
    int ev = gspl_g[l17];
    LDG_Q(0, 0); STS_Q(0, 0);
    LDG_Q(0, 1); STS_Q(0, 1);
    LDG_Q(0, 2); STS_Q(0, 2);
    LDG_Q(0, 3); STS_Q(0, 3);
    __syncthreads();

    for (int p = 0; p < passes; p++) {
        // boundaries for NEXT pass (sentinel region makes p=passes-1 safe)
        int ev_next = gspl_g[(p + 1) * 16 + l17];

        const bool more = (p + 1 < passes);
        const int nb = (p + 1) & 1;
        const float* buf = xs + (p & 1) * BUFW + 2 * lane;

        if (more) LDG_Q(p + 1, 0);
        GATHER(0, 4);
        if (more) { STS_Q(nb, 0); LDG_Q(p + 1, 1); }
        GATHER(4, 8);
        // ---- L1-prefetch next pass's table stream (distance ~1 pass) ----
        {
            int nb0 = __shfl_sync(0xffffffffu, ev_next, 0);
            int nb1 = __shfl_sync(0xffffffffu, ev_next, 16);
            const char* pf = (const char*)(tg + nb0);
            int nbytes = (nb1 - nb0) * (int)sizeof(int2);
            if (lane * 128 < nbytes)
                asm volatile("prefetch.global.L1 [%0];" :: "l"(pf + lane * 128));
        }
        if (more) { STS_Q(nb, 1); LDG_Q(p + 1, 2); }
        GATHER(8, 12);
        if (more) { STS_Q(nb, 2); LDG_Q(p + 1, 3); }
        GATHER(12, 16);
        if (more) STS_Q(nb, 3);

        ev = ev_next;
        __syncthreads();                    // chunk p+1 ready; buf p released
    }

    // ---- transpose through SMEM (STS.64), coalesced store ----
#pragma unroll
    for (int d = 0; d < DPW; d++)
        *(float2*)&xs[(wid * DPW + d) * S + 2 * lane] = acc[d];
    __syncthreads();

    const int total = NDST * TOKS;          // 32768
    for (int i = tid; i < total; i += 1024) {
        int t = i >> 9;                     // token within tile (0..63)
        int c = i & (NDST - 1);             // local dst
        out[(size_t)(token0 + t) * 2048 + col_off + dst_base + c] = xs[c * S + t];
    }
#undef LDG_Q
#undef STS_Q
#undef GATHER
}

// ---------------------------------------------------------------------------
// Launch
// ---------------------------------------------------------------------------
extern "C" void kernel_launch(void* const* d_in, const int* in_sizes, int n_in,
                              void* d_out, int out_size)
{
    // Layout detection: dict order vs signature order (w/m swap harmless).
    const float *xa, *wa, *ma, *xb, *wb, *mb, *xc, *wc, *mc;
    if (in_sizes[1] == 1024 * 4096) {           // dict order
        xa = (const float*)d_in[0]; wa = (const float*)d_in[1]; ma = (const float*)d_in[2];
        xb = (const float*)d_in[3]; wb = (const float*)d_in[4]; mb = (const float*)d_in[5];
        xc = (const float*)d_in[6]; wc = (const float*)d_in[7]; mc = (const float*)d_in[8];
    } else {                                    // signature order
        xa = (const float*)d_in[0]; xb = (const float*)d_in[1]; xc = (const float*)d_in[2];
        wa = (const float*)d_in[3]; wb = (const float*)d_in[4]; wc = (const float*)d_in[5];
        ma = (const float*)d_in[6]; mb = (const float*)d_in[7]; mc = (const float*)d_in[8];
    }
    float* out = (float*)d_out;

    cudaFuncSetAttribute(tract_fused, cudaFuncAttributeMaxDynamicSharedMemorySize,
                         SMEM_BYTES);

    // ---- prep: 128 groups (64 A + 32 B + 32 C), one block each ----
    prep_grouped<<<128, 512>>>(wa, ma, wb, mb, wc, mc);

    // ---- fused sparse gather for all three tracts ----
    tract_fused<<<512, 1024, SMEM_BYTES>>>(xa, xb, xc, out);
}

// round 16
// speedup vs baseline: 1.0340x; 1.0340x over previous
#include <cuda_runtime.h>
#include <cstdint>

// ---------------------------------------------------------------------------
// TractBundle: out = concat( x_a @ (Wa*Ma)^T, x_b @ (Wb*Mb)^T, x_c @ (Wc*Mc)^T )
// Masks: 64/64/32-sparse per row -> compressed sparse-gather.
// R15 (= R13 resubmit, infra failed; prefetch removed to isolate the delta):
// grouped-contiguous (pass,dst)-major table stream, single uniform running
// cursor, per-segment 8-bit packed lengths (one uint4 per pass, zero
// shuffles), even-padded segments (pure int4 loop). R8 staging/epilogue.
// ---------------------------------------------------------------------------

#define CHUNK 256                   // src elements staged per pass
#define S     66                    // smem row stride (EVEN: float2 alignment)
#define TOKS  64                    // tokens per block (2 per lane, float2)
#define NDST  512                   // dst columns per block
#define DPW   16                    // dsts per warp (= group size)
#define BUFW  (CHUNK * S)           // 16896 floats per buffer
#define SMEM_BYTES (2 * BUFW * 4)   // 135168
#define CAPAB 1280                  // entries per group, A/B (16*(64+16) padded)
#define CAPC  640                   // entries per group, C   (16*(32+8)  padded)

// Grouped tables: group g (16 dsts) owns one contiguous stream ordered
// (pass, dst)-major; every (dst,pass) segment padded to EVEN length with
// (0, 0.0f). Entry = ( (src%CHUNK)*S , bits(w*m) ).
__device__ __align__(16) int2 g_tabA[64 * CAPAB];
__device__ __align__(16) int2 g_tabB[32 * CAPAB];
__device__ __align__(16) int2 g_tabC[32 * CAPC];
// Packed padded segment lengths: glen[group][pass] = 16 bytes (one per dst).
__device__ uint4 g_glenA[64 * 16];
__device__ uint4 g_glenB[32 * 16];
__device__ uint4 g_glenC[32 * 8];

// ---------------------------------------------------------------------------
// Prep: one block per group of 16 dst rows (128 groups), 512 threads.
// padded-even counts -> (pass,dst)-major scan -> scatter + zero-pad + glen.
// ---------------------------------------------------------------------------
__global__ __launch_bounds__(512)
void prep_grouped(const float* __restrict__ wa, const float* __restrict__ ma,
                  const float* __restrict__ wb, const float* __restrict__ mb,
                  const float* __restrict__ wc, const float* __restrict__ mc)
{
    __shared__ int soff[16][16];    // [dst][pass] group-relative offsets
    __shared__ int scnt[16][16];    // [dst][pass] padded counts

    const int tid  = threadIdx.x;
    const int lane = tid & 31;
    const int r    = tid >> 5;      // warp = row within group

    const float *W, *M; int2* tab; uint4* glen;
    int src, group, cap;
    int gb = blockIdx.x;
    if (gb < 64)      { W = wa; M = ma; tab = g_tabA; glen = g_glenA;
                        src = 4096; group = gb;      cap = CAPAB; }
    else if (gb < 96) { W = wb; M = mb; tab = g_tabB; glen = g_glenB;
                        src = 4096; group = gb - 64; cap = CAPAB; }
    else              { W = wc; M = mc; tab = g_tabC; glen = g_glenC;
                        src = 2048; group = gb - 96; cap = CAPC; }

    const int passes = src / CHUNK;
    const int row = group * 16 + r;
    const float* wr = W + (size_t)row * src;
    const float* mr = M + (size_t)row * src;

    // ---- sweep 1: padded (even) nnz count per chunk ----
    for (int c = 0; c < passes; c++) {
        int cnt = 0;
#pragma unroll
        for (int i = 0; i < CHUNK / 32; i++)
            cnt += (mr[c * CHUNK + i * 32 + lane] != 0.0f);
#pragma unroll
        for (int o = 16; o; o >>= 1) cnt += __shfl_xor_sync(0xffffffffu, cnt, o);
        if (lane == 0) scnt[r][c] = (cnt + 1) & ~1;
    }
    __syncthreads();

    // ---- scan in (pass, dst)-major order ----
    if (tid == 0) {
        int run = 0;
        for (int p = 0; p < passes; p++)
            for (int d = 0; d < 16; d++) { soff[d][p] = run; run += scnt[d][p]; }
    }
    __syncthreads();

    // ---- write packed lengths: one uint4 per pass ----
    if (tid < passes) {
        unsigned v[4] = {0, 0, 0, 0};
        for (int d = 0; d < 16; d++)
            v[d >> 2] |= (unsigned)scnt[d][tid] << (8 * (d & 3));
        glen[group * passes + tid] = make_uint4(v[0], v[1], v[2], v[3]);
    }

    // ---- sweep 2: scatter entries + zero-pad odd segments ----
    int2* tg = tab + (size_t)group * cap;
    for (int c = 0; c < passes; c++) {
        int start = soff[r][c];
        int base = start;
        for (int i = 0; i < CHUNK / 32; i++) {
            int s = c * CHUNK + i * 32 + lane;
            float mv = mr[s];
            unsigned bits = __ballot_sync(0xffffffffu, mv != 0.0f);
            if (mv != 0.0f) {
                int pos = base + __popc(bits & ((1u << lane) - 1u));
                tg[pos] = make_int2((s & (CHUNK - 1)) * S, __float_as_int(wr[s] * mv));
            }
            base += __popc(bits);
        }
        if (lane == 0 && ((base - start) & 1))
            tg[base] = make_int2(0, 0);     // zero-weight pad -> even length
    }
}

// ---------------------------------------------------------------------------
// Fused gather kernel, 512 blocks x 1024 threads (32 warps).
//   [0,256)   tract A: tile = b>>1 (64-token tiles), dstblk = b&1
//   [256,384) tract B;  [384,512) tract C
// Warp w owns a 16-dst group; one continuous even-length int4 stream with a
// uniform running cursor e. Per pass: one uint4 length load, register-quarter
// x staging interleaved with 4-dst gathers, one __syncthreads.
// ---------------------------------------------------------------------------
__global__ __launch_bounds__(1024, 1)
void tract_fused(const float* __restrict__ xa,
                 const float* __restrict__ xb,
                 const float* __restrict__ xc,
                 float* __restrict__ out)
{
    extern __shared__ float xs[];
    const int tid  = threadIdx.x;
    const int lane = tid & 31;
    const int wid  = tid >> 5;

    // ---- block -> (tract, tile, dst block) dispatch ----
    const float* x; const int2* tab; const uint4* glen;
    int src, passes, col_off, token0, dst_base, group, cap;
    int b = blockIdx.x;
    if (b < 256) {
        x = xa; tab = g_tabA; glen = g_glenA;
        src = 4096; passes = 16; cap = CAPAB;
        col_off = 0; token0 = (b >> 1) * TOKS; dst_base = (b & 1) * NDST;
        group = (b & 1) * 32 + wid;
    } else if (b < 384) {
        x = xb; tab = g_tabB; glen = g_glenB;
        src = 4096; passes = 16; cap = CAPAB;
        col_off = 1024; token0 = (b - 256) * TOKS; dst_base = 0;
        group = wid;
    } else {
        x = xc; tab = g_tabC; glen = g_glenC;
        src = 2048; passes = 8; cap = CAPC;
        col_off = 1536; token0 = (b - 384) * TOKS; dst_base = 0;
        group = wid;
    }

    const int2* tg      = tab + (size_t)group * cap;   // warp's stream
    const uint4* glen_g = glen + group * passes;
    const float* xr0 = x + (size_t)(token0 + 2 * wid) * src;
    const float* xr1 = xr0 + src;

    float2 st[2];                           // staged quarter (4 regs)

    // LDG quarter q (0..3) of chunk p
#define LDG_Q(p, q) do {                                                     \
        int _b = (p) * CHUNK + (q) * 64 + lane;                              \
        st[0] = make_float2(xr0[_b],      xr1[_b]);                          \
        st[1] = make_float2(xr0[_b + 32], xr1[_b + 32]);                     \
    } while (0)

    // STS quarter q into buffer bb (STS.64)
#define STS_Q(bb, q) do {                                                    \
        float* _d = xs + (bb) * BUFW + 2 * wid;                              \
        *(float2*)&_d[((q) * 64 + lane) * S]      = st[0];                   \
        *(float2*)&_d[((q) * 64 + lane + 32) * S] = st[1];                   \
    } while (0)

    // gather 4 dsts whose padded lengths are the 4 bytes of word Wd.
    // e is a uniform running cursor over the warp's contiguous stream.
#define GATHER4(Wd) do {                                                     \
        unsigned _w = (Wd);                                                  \
        _Pragma("unroll")                                                    \
        for (int _d = 0; _d < 4; _d++) {                                     \
            int _len = (_w >> (8 * _d)) & 255;                               \
            int _e1 = e + _len;                                              \
            float a0x = 0.f, a0y = 0.f, a1x = 0.f, a1y = 0.f;                \
            for (; e < _e1; e += 2) {                                        \
                int4 q = *(const int4*)&tg[e];                               \
                float2 xv0 = *(const float2*)(buf + q.x);                    \
                float2 xv1 = *(const float2*)(buf + q.z);                    \
                float w0 = __int_as_float(q.y);                              \
                float w1 = __int_as_float(q.w);                              \
                a0x = fmaf(w0, xv0.x, a0x);                                  \
                a0y = fmaf(w0, xv0.y, a0y);                                  \
                a1x = fmaf(w1, xv1.x, a1x);                                  \
                a1y = fmaf(w1, xv1.y, a1y);                                  \
            }                                                                \
            acc[dacc].x += a0x + a1x;                                        \
            acc[dacc].y += a0y + a1y;                                        \
            dacc++;                                                          \
        }                                                                    \
    } while (0)

    float2 acc[DPW];
#pragma unroll
    for (int d = 0; d < DPW; d++) acc[d] = make_float2(0.0f, 0.0f);

    // ---- prologue: stage chunk 0 into buffer 0 ----
    LDG_Q(0, 0); STS_Q(0, 0);
    LDG_Q(0, 1); STS_Q(0, 1);
    LDG_Q(0, 2); STS_Q(0, 2);
    LDG_Q(0, 3); STS_Q(0, 3);
    __syncthreads();

    int e = 0;                              // uniform stream cursor

    for (int p = 0; p < passes; p++) {
        uint4 L = glen_g[p];                // this pass's 16 packed lengths

        const bool more = (p + 1 < passes);
        const int nb = (p + 1) & 1;
        const float* buf = xs + (p & 1) * BUFW + 2 * lane;
        int dacc = 0;

        if (more) LDG_Q(p + 1, 0);
        GATHER4(L.x);
        if (more) { STS_Q(nb, 0); LDG_Q(p + 1, 1); }
        GATHER4(L.y);
        if (more) { STS_Q(nb, 1); LDG_Q(p + 1, 2); }
        GATHER4(L.z);
        if (more) { STS_Q(nb, 2); LDG_Q(p + 1, 3); }
        GATHER4(L.w);
        if (more) STS_Q(nb, 3);

        __syncthreads();                    // chunk p+1 ready; buf p released
    }

    // ---- transpose through SMEM (STS.64), coalesced store ----
#pragma unroll
    for (int d = 0; d < DPW; d++)
        *(float2*)&xs[(wid * DPW + d) * S + 2 * lane] = acc[d];
    __syncthreads();

    const int total = NDST * TOKS;          // 32768
    for (int i = tid; i < total; i += 1024) {
        int t = i >> 9;                     // token within tile (0..63)
        int c = i & (NDST - 1);             // local dst
        out[(size_t)(token0 + t) * 2048 + col_off + dst_base + c] = xs[c * S + t];
    }
#undef LDG_Q
#undef STS_Q
#undef GATHER4
}

// ---------------------------------------------------------------------------
// Launch
// ---------------------------------------------------------------------------
extern "C" void kernel_launch(void* const* d_in, const int* in_sizes, int n_in,
                              void* d_out, int out_size)
{
    // Layout detection: dict order vs signature order (w/m swap harmless).
    const float *xa, *wa, *ma, *xb, *wb, *mb, *xc, *wc, *mc;
    if (in_sizes[1] == 1024 * 4096) {           // dict order
        xa = (const float*)d_in[0]; wa = (const float*)d_in[1]; ma = (const float*)d_in[2];
        xb = (const float*)d_in[3]; wb = (const float*)d_in[4]; mb = (const float*)d_in[5];
        xc = (const float*)d_in[6]; wc = (const float*)d_in[7]; mc = (const float*)d_in[8];
    } else {                                    // signature order
        xa = (const float*)d_in[0]; xb = (const float*)d_in[1]; xc = (const float*)d_in[2];
        wa = (const float*)d_in[3]; wb = (const float*)d_in[4]; wc = (const float*)d_in[5];
        ma = (const float*)d_in[6]; mb = (const float*)d_in[7]; mc = (const float*)d_in[8];
    }
    float* out = (float*)d_out;

    cudaFuncSetAttribute(tract_fused, cudaFuncAttributeMaxDynamicSharedMemorySize,
                         SMEM_BYTES);

    // ---- prep: 128 groups (64 A + 32 B + 32 C), one block each ----
    prep_grouped<<<128, 512>>>(wa, ma, wb, mb, wc, mc);

    // ---- fused sparse gather for all three tracts ----
    tract_fused<<<512, 1024, SMEM_BYTES>>>(xa, xb, xc, out);
}